// round 1
// baseline (speedup 1.0000x reference)
#include <cuda_runtime.h>
#include <cuda_bf16.h>
#include <cstdint>
#include <math.h>

// ---------------------------------------------------------------------------
// Problem constants
// ---------------------------------------------------------------------------
#define TT   2048
#define EDIM 256
#define H2D  256
#define LDIM 32
#define RTOT 2048   // 2 dirs * 4 gates * 256

// ---------------------------------------------------------------------------
// Scratch (static device globals: the sanctioned no-alloc workaround)
// ---------------------------------------------------------------------------
__device__ float g_zin[TT * RTOT];      // 16 MB: [t][dir*1024 + gate*256 + h]
__device__ float g_hs[TT * 512];        // 4 MB:  [t][dir*256 + h]
__device__ float g_logits[TT * LDIM];   // 256 KB

// ---------------------------------------------------------------------------
// Helpers
// ---------------------------------------------------------------------------
__device__ __forceinline__ uint32_t s2u(const void* p) {
    uint32_t a;
    asm("{ .reg .u64 t; cvta.to.shared.u64 t, %1; cvt.u32.u64 %0, t; }"
        : "=r"(a) : "l"(p));
    return a;
}

__device__ __forceinline__ void cluster_sync_() {
    asm volatile("barrier.cluster.arrive.aligned;\n\t"
                 "barrier.cluster.wait.aligned;" ::: "memory");
}

__device__ __forceinline__ uint32_t my_ctarank() {
    uint32_t r;
    asm("mov.u32 %0, %%cluster_ctarank;" : "=r"(r));
    return r;
}

__device__ __forceinline__ void st_cluster_f32(uint32_t saddr, uint32_t rank, float v) {
    uint32_t pa;
    asm("mapa.shared::cluster.u32 %0, %1, %2;" : "=r"(pa) : "r"(saddr), "r"(rank));
    asm volatile("st.shared::cluster.f32 [%0], %1;" :: "r"(pa), "f"(v) : "memory");
}

// ---------------------------------------------------------------------------
// Kernel 1: Zin[t][col] = emb[ids[t]] @ Wih^T + b   (col = dir*1024 + gate row)
// 64x64 tiles, BK=32, 256 threads, 4x4 per thread.
// ---------------------------------------------------------------------------
__global__ __launch_bounds__(256) void zin_kernel(
    const int* __restrict__ ids, const float* __restrict__ emb,
    const float* __restrict__ wihf, const float* __restrict__ wihb,
    const float* __restrict__ bf, const float* __restrict__ bb)
{
    __shared__ float As[32][68];
    __shared__ float Bs[32][68];
    __shared__ int gids[64];

    const int tid = threadIdx.x;
    const int tx = tid & 15;        // 0..15 -> col group
    const int ty = tid >> 4;        // 0..15 -> row group
    const int tRow = blockIdx.y * 64;
    const int nCol = blockIdx.x * 64;

    if (tid < 64) gids[tid] = ids[tRow + tid];
    __syncthreads();

    float acc[4][4];
#pragma unroll
    for (int i = 0; i < 4; i++)
#pragma unroll
        for (int j = 0; j < 4; j++) acc[i][j] = 0.f;

    for (int kk = 0; kk < EDIM; kk += 32) {
#pragma unroll
        for (int u = 0; u < 2; u++) {
            int idx = tid + u * 256;        // 0..511
            int row = idx >> 3;             // 0..63
            int c4  = (idx & 7) * 4;        // 0..28
            // A tile: gathered embedding rows
            const float4 av = *(const float4*)(emb + (size_t)gids[row] * EDIM + kk + c4);
            As[c4 + 0][row] = av.x; As[c4 + 1][row] = av.y;
            As[c4 + 2][row] = av.z; As[c4 + 3][row] = av.w;
            // B tile: stacked gate-weight rows (fwd rows 0..1023, bwd 1024..2047)
            int brow = nCol + row;
            const float* bp = (brow < 1024)
                ? (wihf + (size_t)brow * EDIM)
                : (wihb + (size_t)(brow - 1024) * EDIM);
            const float4 bv = *(const float4*)(bp + kk + c4);
            Bs[c4 + 0][row] = bv.x; Bs[c4 + 1][row] = bv.y;
            Bs[c4 + 2][row] = bv.z; Bs[c4 + 3][row] = bv.w;
        }
        __syncthreads();
#pragma unroll
        for (int k = 0; k < 32; k++) {
            const float4 av = *(const float4*)&As[k][ty * 4];
            const float4 bv = *(const float4*)&Bs[k][tx * 4];
            const float ar[4] = {av.x, av.y, av.z, av.w};
            const float br[4] = {bv.x, bv.y, bv.z, bv.w};
#pragma unroll
            for (int i = 0; i < 4; i++)
#pragma unroll
                for (int j = 0; j < 4; j++) acc[i][j] += ar[i] * br[j];
        }
        __syncthreads();
    }

    const int colBase = nCol + tx * 4;
    float bias[4];
#pragma unroll
    for (int j = 0; j < 4; j++) {
        int c = colBase + j;
        bias[j] = (c < 1024) ? bf[c] : bb[c - 1024];
    }
#pragma unroll
    for (int i = 0; i < 4; i++) {
        int row = tRow + ty * 4 + i;
        float4 o;
        o.x = acc[i][0] + bias[0];
        o.y = acc[i][1] + bias[1];
        o.z = acc[i][2] + bias[2];
        o.w = acc[i][3] + bias[3];
        *(float4*)(g_zin + (size_t)row * RTOT + colBase) = o;
    }
}

// ---------------------------------------------------------------------------
// Kernel 2: BiLSTM recurrence. 2 clusters of 8 CTAs (fwd / bwd).
// Each CTA owns 32 h-outputs (128 gate rows); W_hh slice lives in registers
// (128 floats/thread). h exchanged via DSMEM + cluster.sync, double-buffered.
// ---------------------------------------------------------------------------
__global__ void __launch_bounds__(256, 1) __cluster_dims__(8, 1, 1)
lstm_kernel(const float* __restrict__ whhf, const float* __restrict__ whhb,
            const float* __restrict__ h0, const float* __restrict__ c0)
{
    __shared__ float h_s[2][256];
    __shared__ float z_s[128];

    const int tid  = threadIdx.x;
    const int dir  = blockIdx.x >> 3;
    const uint32_t rank = my_ctarank();

    const float* whh = dir ? whhb : whhf;

    const int half = tid & 1;        // which 128-col half of the dot product
    const int lr   = tid >> 1;       // local gate row 0..127
    const int gate = lr >> 5;        // 0..3 (i,f,g,o)
    const int j    = lr & 31;
    const int grow = gate * 256 + (int)rank * 32 + j;   // global gate row in [0,1024)

    // register-resident weight slice: 128 floats
    float4 w4[32];
    {
        const float4* wrow = (const float4*)(whh + (size_t)grow * H2D + half * 128);
#pragma unroll
        for (int i = 0; i < 32; i++) w4[i] = wrow[i];
    }

    const int hidx = (int)rank * 32 + tid;   // valid for tid < 32
    float c_reg = (tid < 32) ? c0[dir * H2D + hidx] : 0.f;

    h_s[0][tid] = h0[dir * H2D + tid];
    const int zbase = dir * 1024 + (int)rank * 32;

    const uint32_t haddr0 = s2u(&h_s[0][0]);
    const uint32_t haddr1 = s2u(&h_s[1][0]);

    cluster_sync_();

    for (int s = 0; s < TT; s++) {
        const int t   = dir ? (TT - 1 - s) : s;
        const int buf = s & 1;

        // prefetch Zin gate contributions (independent of h; L2 latency hidden)
        float zi_in = 0.f, zf_in = 0.f, zg_in = 0.f, zo_in = 0.f;
        if (tid < 32) {
            const float* zrow = g_zin + (size_t)t * RTOT + zbase + tid;
            zi_in = zrow[0];
            zf_in = zrow[256];
            zg_in = zrow[512];
            zo_in = zrow[768];
        }

        // matvec partial: 128 MACs from registers, h from smem (broadcast)
        const float* hb = &h_s[buf][half * 128];
        float acc = 0.f;
#pragma unroll
        for (int k = 0; k < 32; k++) {
            const int ii = half ? ((k + 1) & 31) : k;   // stagger kills bank conflict
            const float4 hv = *(const float4*)(hb + 4 * ii);
            const float4 wv = w4[ii];
            acc += wv.x * hv.x + wv.y * hv.y + wv.z * hv.z + wv.w * hv.w;
        }
        acc += __shfl_xor_sync(0xffffffffu, acc, 1);
        if (!half) z_s[lr] = acc;
        __syncthreads();

        if (tid < 32) {
            const float zi = z_s[tid]      + zi_in;
            const float zf = z_s[32 + tid] + zf_in;
            const float zg = z_s[64 + tid] + zg_in;
            const float zo = z_s[96 + tid] + zo_in;
            const float ig = 1.f / (1.f + expf(-zi));
            const float fg = 1.f / (1.f + expf(-zf));
            const float gg = tanhf(zg);
            const float og = 1.f / (1.f + expf(-zo));
            c_reg = fg * c_reg + ig * gg;
            const float h = og * tanhf(c_reg);

            g_hs[(size_t)t * 512 + dir * H2D + hidx] = h;

            // broadcast new h element to every CTA in the cluster (incl. self)
            const uint32_t dst = (buf ? haddr0 : haddr1) + 4u * (uint32_t)hidx;
#pragma unroll
            for (uint32_t r = 0; r < 8; r++) st_cluster_f32(dst, r, h);
        }
        cluster_sync_();   // release/acquire: DSMEM writes visible next step
    }
}

// ---------------------------------------------------------------------------
// Kernel 3: logits = hs @ w_lin^T + b_lin.  One warp per timestep.
// ---------------------------------------------------------------------------
__global__ __launch_bounds__(256) void linear_kernel(
    const float* __restrict__ wlin, const float* __restrict__ blin)
{
    const int warp = threadIdx.x >> 5;
    const int lane = threadIdx.x & 31;
    const int t = blockIdx.x * 8 + warp;

    const float4* hrow = (const float4*)(g_hs + (size_t)t * 512);
    const float4* wrow = (const float4*)(wlin + (size_t)lane * 512);
    float acc = blin[lane];
#pragma unroll 8
    for (int m = 0; m < 128; m++) {
        const float4 h4 = hrow[m];
        const float4 w4 = wrow[m];
        acc += h4.x * w4.x + h4.y * w4.y + h4.z * w4.z + h4.w * w4.w;
    }
    g_logits[(size_t)t * LDIM + lane] = acc;
}

// ---------------------------------------------------------------------------
// Kernel 4: CRF negative log-likelihood. Single warp, E = exp(trans) matvec.
// ---------------------------------------------------------------------------
__global__ void crf_kernel(const float* __restrict__ trans,
                           const int* __restrict__ target,
                           float* __restrict__ out)
{
    __shared__ float tr_s[32 * 33];
    __shared__ float E_s[32 * 33];
    __shared__ float e_s[32];

    const int tid = threadIdx.x;   // blockDim = 32

    for (int i = tid; i < 1024; i += 32) {
        const int n = i >> 5, p = i & 31;
        const float v = trans[i];
        tr_s[n * 33 + p] = v;
        E_s[n * 33 + p]  = __expf(v);   // exp(-1e4) -> exactly 0
    }
    __syncwarp();

    // ---- gold path score ----
    float gs = 0.f;
    for (int t = tid; t < TT; t += 32) {
        const int nxt  = target[t];
        const int prev = (t == 0) ? 0 : target[t - 1];   // CLS = 0
        gs += tr_s[nxt * 33 + prev] + g_logits[(size_t)t * LDIM + nxt];
    }
#pragma unroll
    for (int o = 16; o; o >>= 1) gs += __shfl_xor_sync(0xffffffffu, gs, o);
    gs += tr_s[31 * 33 + target[TT - 1]];                // trans[SEP, last]

    // ---- forward algorithm ----
    const int n = tid;
    float a = tr_s[n * 33 + 0] + g_logits[n];            // step 0: only CLS survives
    const float* EP = &E_s[n * 33];

    for (int t = 1; t < TT; t++) {
        const float em = g_logits[(size_t)t * LDIM + n];
        const float M  = __shfl_sync(0xffffffffu, a, 1); // any finite alpha works
        e_s[n] = __expf(a - M);                          // a=-inf -> 0
        __syncwarp();
        float a0 = 0.f, a1 = 0.f, a2 = 0.f, a3 = 0.f;
#pragma unroll
        for (int p = 0; p < 32; p += 4) {
            a0 += e_s[p]     * EP[p];
            a1 += e_s[p + 1] * EP[p + 1];
            a2 += e_s[p + 2] * EP[p + 2];
            a3 += e_s[p + 3] * EP[p + 3];
        }
        const float ssum = (a0 + a1) + (a2 + a3);
        a = __logf(ssum) + M + em;                        // ssum=0 -> -inf (blocked row)
        __syncwarp();
    }

    // forward_score = logsumexp(alpha + trans[SEP, :])
    const float v = a + tr_s[31 * 33 + n];
    float m = v;
#pragma unroll
    for (int o = 16; o; o >>= 1) m = fmaxf(m, __shfl_xor_sync(0xffffffffu, m, o));
    float ex = __expf(v - m);
#pragma unroll
    for (int o = 16; o; o >>= 1) ex += __shfl_xor_sync(0xffffffffu, ex, o);
    const float fwd = __logf(ex) + m;

    if (tid == 0) out[0] = fwd - gs;
}

// ---------------------------------------------------------------------------
// Launch
// ---------------------------------------------------------------------------
extern "C" void kernel_launch(void* const* d_in, const int* in_sizes, int n_in,
                              void* d_out, int out_size)
{
    const int*   ids    = (const int*)  d_in[0];
    // d_in[1] = attention_mask (unused by reference)
    const int*   target = (const int*)  d_in[2];
    const float* emb    = (const float*)d_in[3];
    const float* wihf   = (const float*)d_in[4];
    const float* whhf   = (const float*)d_in[5];
    const float* bf     = (const float*)d_in[6];
    const float* wihb   = (const float*)d_in[7];
    const float* whhb   = (const float*)d_in[8];
    const float* bb     = (const float*)d_in[9];
    const float* wlin   = (const float*)d_in[10];
    const float* blin   = (const float*)d_in[11];
    const float* trans  = (const float*)d_in[12];
    const float* h0     = (const float*)d_in[13];
    const float* c0     = (const float*)d_in[14];

    dim3 g1(RTOT / 64, TT / 64);
    zin_kernel<<<g1, 256>>>(ids, emb, wihf, wihb, bf, bb);
    lstm_kernel<<<16, 256>>>(whhf, whhb, h0, c0);
    linear_kernel<<<TT / 8, 256>>>(wlin, blin);
    crf_kernel<<<1, 32>>>(trans, target, (float*)d_out);
}

// round 3
// speedup vs baseline: 1.2651x; 1.2651x over previous
#include <cuda_runtime.h>
#include <cuda_bf16.h>
#include <cstdint>
#include <math.h>

// ---------------------------------------------------------------------------
// Problem constants
// ---------------------------------------------------------------------------
#define TT   2048
#define EDIM 256
#define H2D  256
#define LDIM 32
#define RTOT 2048   // 2 dirs * 4 gates * 256

// ---------------------------------------------------------------------------
// Scratch
// ---------------------------------------------------------------------------
__device__ float g_zin[TT * RTOT];      // 16 MB: [t][dir*1024 + gate*256 + h]
__device__ float g_hs[TT * 512];        // 4 MB:  [t][dir*256 + h]
__device__ float g_logits[TT * LDIM];   // 256 KB

// ---------------------------------------------------------------------------
// Helpers
// ---------------------------------------------------------------------------
__device__ __forceinline__ uint32_t s2u(const void* p) {
    uint32_t a;
    asm("{ .reg .u64 t; cvta.to.shared.u64 t, %1; cvt.u32.u64 %0, t; }"
        : "=r"(a) : "l"(p));
    return a;
}
__device__ __forceinline__ void cluster_sync_() {
    asm volatile("barrier.cluster.arrive.aligned;\n\t"
                 "barrier.cluster.wait.aligned;" ::: "memory");
}
__device__ __forceinline__ uint32_t my_ctarank() {
    uint32_t r;
    asm("mov.u32 %0, %%cluster_ctarank;" : "=r"(r));
    return r;
}
__device__ __forceinline__ uint32_t mapa_(uint32_t a, uint32_t r) {
    uint32_t d;
    asm("mapa.shared::cluster.u32 %0, %1, %2;" : "=r"(d) : "r"(a), "r"(r));
    return d;
}
__device__ __forceinline__ unsigned long long ffma2(unsigned long long a,
                                                    unsigned long long b,
                                                    unsigned long long c) {
    unsigned long long d;
    asm("fma.rn.f32x2 %0, %1, %2, %3;" : "=l"(d) : "l"(a), "l"(b), "l"(c));
    return d;
}
__device__ __forceinline__ float lo32(unsigned long long v) { return __uint_as_float((unsigned)v); }
__device__ __forceinline__ float hi32(unsigned long long v) { return __uint_as_float((unsigned)(v >> 32)); }

__device__ __forceinline__ void st_async_f32(uint32_t daddr, float v, uint32_t dmbar) {
    asm volatile("st.async.shared::cluster.mbarrier::complete_tx::bytes.f32 [%0], %1, [%2];"
                 :: "r"(daddr), "f"(v), "r"(dmbar) : "memory");
}

#define MBAR_INIT(a, n) \
    asm volatile("mbarrier.init.shared.b64 [%0], %1;" :: "r"(a), "r"((uint32_t)(n)) : "memory")
#define MBAR_EXPECT_TX(a, n) \
    asm volatile("mbarrier.arrive.expect_tx.shared.b64 _, [%0], %1;" :: "r"(a), "r"((uint32_t)(n)) : "memory")

__device__ __forceinline__ void mbar_wait_parity(uint32_t mbar, uint32_t parity) {
    uint32_t done;
    asm volatile(
        "{\n\t.reg .pred p;\n\t"
        "mbarrier.try_wait.parity.acquire.cta.shared::cta.b64 p, [%1], %2;\n\t"
        "selp.b32 %0, 1, 0, p;\n\t}"
        : "=r"(done) : "r"(mbar), "r"(parity) : "memory");
    if (!done) {
        asm volatile(
            "{\n\t.reg .pred P1;\n\t"
            "WL_%=:\n\t"
            "mbarrier.try_wait.parity.acquire.cta.shared::cta.b64 P1, [%0], %1, 0x989680;\n\t"
            "@P1 bra.uni WD_%=;\n\t"
            "bra.uni WL_%=;\n\t"
            "WD_%=:\n\t}"
            :: "r"(mbar), "r"(parity) : "memory");
    }
}

__device__ __forceinline__ float fsigm(float x) { return 1.f / (1.f + __expf(-x)); }
__device__ __forceinline__ float ftanh(float x) {
    return __fmaf_rn(2.f, 1.f / (1.f + __expf(-2.f * x)), -1.f);
}

// ---------------------------------------------------------------------------
// Kernel 1: Zin[t][col] = emb[ids[t]] @ Wih^T + b
// ---------------------------------------------------------------------------
__global__ __launch_bounds__(256) void zin_kernel(
    const int* __restrict__ ids, const float* __restrict__ emb,
    const float* __restrict__ wihf, const float* __restrict__ wihb,
    const float* __restrict__ bf, const float* __restrict__ bb)
{
    __shared__ float As[32][68];
    __shared__ float Bs[32][68];
    __shared__ int gids[64];

    const int tid = threadIdx.x;
    const int tx = tid & 15;
    const int ty = tid >> 4;
    const int tRow = blockIdx.y * 64;
    const int nCol = blockIdx.x * 64;

    if (tid < 64) gids[tid] = ids[tRow + tid];
    __syncthreads();

    float acc[4][4];
#pragma unroll
    for (int i = 0; i < 4; i++)
#pragma unroll
        for (int j = 0; j < 4; j++) acc[i][j] = 0.f;

    for (int kk = 0; kk < EDIM; kk += 32) {
#pragma unroll
        for (int u = 0; u < 2; u++) {
            int idx = tid + u * 256;
            int row = idx >> 3;
            int c4  = (idx & 7) * 4;
            const float4 av = *(const float4*)(emb + (size_t)gids[row] * EDIM + kk + c4);
            As[c4 + 0][row] = av.x; As[c4 + 1][row] = av.y;
            As[c4 + 2][row] = av.z; As[c4 + 3][row] = av.w;
            int brow = nCol + row;
            const float* bp = (brow < 1024)
                ? (wihf + (size_t)brow * EDIM)
                : (wihb + (size_t)(brow - 1024) * EDIM);
            const float4 bv = *(const float4*)(bp + kk + c4);
            Bs[c4 + 0][row] = bv.x; Bs[c4 + 1][row] = bv.y;
            Bs[c4 + 2][row] = bv.z; Bs[c4 + 3][row] = bv.w;
        }
        __syncthreads();
#pragma unroll
        for (int k = 0; k < 32; k++) {
            const float4 av = *(const float4*)&As[k][ty * 4];
            const float4 bv = *(const float4*)&Bs[k][tx * 4];
            const float ar[4] = {av.x, av.y, av.z, av.w};
            const float br[4] = {bv.x, bv.y, bv.z, bv.w};
#pragma unroll
            for (int i = 0; i < 4; i++)
#pragma unroll
                for (int j = 0; j < 4; j++) acc[i][j] += ar[i] * br[j];
        }
        __syncthreads();
    }

    const int colBase = nCol + tx * 4;
    float bias[4];
#pragma unroll
    for (int j = 0; j < 4; j++) {
        int c = colBase + j;
        bias[j] = (c < 1024) ? bf[c] : bb[c - 1024];
    }
#pragma unroll
    for (int i = 0; i < 4; i++) {
        int row = tRow + ty * 4 + i;
        float4 o;
        o.x = acc[i][0] + bias[0];
        o.y = acc[i][1] + bias[1];
        o.z = acc[i][2] + bias[2];
        o.w = acc[i][3] + bias[3];
        *(float4*)(g_zin + (size_t)row * RTOT + colBase) = o;
    }
}

// ---------------------------------------------------------------------------
// Kernel 2: BiLSTM recurrence. 2 clusters of 16 CTAs (fwd / bwd).
// Each CTA: 16 h outputs = 64 gate rows. Thread (lr = t>>2, q = t&3) owns
// 64 weight cols of one gate row as 32 packed f32x2 registers.
// h exchange: st.async -> remote smem + mbarrier complete_tx, double-buffered.
// ---------------------------------------------------------------------------
__global__ void __launch_bounds__(256, 1) __cluster_dims__(16, 1, 1)
lstm_kernel(const float* __restrict__ whhf, const float* __restrict__ whhb,
            const float* __restrict__ h0, const float* __restrict__ c0)
{
    __shared__ float h_s[2][256];
    __shared__ float z_s[64];
    __shared__ unsigned long long mbar[2];

    const int tid  = threadIdx.x;
    const int dir  = blockIdx.x >> 4;
    const uint32_t rank = my_ctarank();

    const int q    = tid & 3;        // column quarter (64 cols)
    const int lr   = tid >> 2;       // local gate row 0..63
    const int gate = lr >> 4;
    const int jr   = lr & 15;
    const int grow = gate * 256 + (int)rank * 16 + jr;

    const float* whh = dir ? whhb : whhf;

    // 64 weights as 32 f32x2, ordered with the staggered (bank-conflict-free)
    // chunk schedule m = (k + 2q) & 15
    unsigned long long w2[32];
    {
        const float* wr = whh + (size_t)grow * H2D + q * 64;
#pragma unroll
        for (int k = 0; k < 16; k++) {
            int m = (k + 2 * q) & 15;
            const unsigned long long* p = (const unsigned long long*)(wr + m * 4);
            w2[2 * k]     = p[0];
            w2[2 * k + 1] = p[1];
        }
    }

    const int jj  = tid & 15;        // h index within this CTA's slice (writers)
    const int grp = tid >> 4;        // redundancy group; writers: grp < 4

    float c_reg = 0.f;
    if (tid < 64) c_reg = c0[dir * H2D + (int)rank * 16 + jj];

    h_s[0][tid] = h0[dir * H2D + tid];

    // Precompute remote store targets (4 destination CTAs per writer thread)
    uint32_t dst_h[2][4], dst_m[2][4];
    if (tid < 64) {
        const uint32_t off = 4u * ((uint32_t)rank * 16 + (uint32_t)jj);
        const uint32_t h0a = s2u(&h_s[0][0]);
        const uint32_t h1a = s2u(&h_s[1][0]);
        const uint32_t m0a = s2u(&mbar[0]);
        const uint32_t m1a = s2u(&mbar[1]);
#pragma unroll
        for (int u = 0; u < 4; u++) {
            const uint32_t r = (uint32_t)(grp * 4 + u);
            dst_h[0][u] = mapa_(h0a, r) + off;
            dst_h[1][u] = mapa_(h1a, r) + off;
            dst_m[0][u] = mapa_(m0a, r);
            dst_m[1][u] = mapa_(m1a, r);
        }
    }

    const uint32_t mb0 = s2u(&mbar[0]);
    const uint32_t mb1 = s2u(&mbar[1]);
    if (tid == 0) {
        MBAR_INIT(mb0, 1);
        MBAR_INIT(mb1, 1);
        MBAR_EXPECT_TX(mb0, 1024);   // receives step-1 stores (buf 0)
        MBAR_EXPECT_TX(mb1, 1024);   // receives step-0 stores (buf 1)
    }
    __syncthreads();
    cluster_sync_();                  // mbarrier init visible cluster-wide

    const int zbase = dir * 1024 + (int)rank * 16 + jj;
    uint32_t ph0 = 0, ph1 = 0;

    for (int s = 0; s < TT; s++) {
        const int t = dir ? (TT - 1 - s) : s;
        const int b = s & 1;

        if (s > 0) {
            if (b) { mbar_wait_parity(mb1, ph1); ph1 ^= 1; if (tid == 0) MBAR_EXPECT_TX(mb1, 1024); }
            else   { mbar_wait_parity(mb0, ph0); ph0 ^= 1; if (tid == 0) MBAR_EXPECT_TX(mb0, 1024); }
        }

        // prefetch Zin (independent of h; hides L2 latency under the matvec)
        float zi = 0.f, zf = 0.f, zg = 0.f, zo = 0.f;
        if (tid < 64) {
            const float* zr = g_zin + (size_t)t * RTOT + zbase;
            zi = zr[0]; zf = zr[256]; zg = zr[512]; zo = zr[768];
        }

        // matvec partial: 32 packed f32x2 FMAs, 2 independent accumulators
        const ulonglong2* hp = (const ulonglong2*)&h_s[b][q * 64];
        unsigned long long a0 = 0ull, a1 = 0ull;
#pragma unroll
        for (int k = 0; k < 16; k++) {
            const int m = (k + 2 * q) & 15;
            const ulonglong2 hv = hp[m];
            a0 = ffma2(w2[2 * k],     hv.x, a0);
            a1 = ffma2(w2[2 * k + 1], hv.y, a1);
        }
        float part = (lo32(a0) + hi32(a0)) + (lo32(a1) + hi32(a1));
        part += __shfl_xor_sync(0xffffffffu, part, 1);
        part += __shfl_xor_sync(0xffffffffu, part, 2);
        if (q == 0) z_s[lr] = part;
        __syncthreads();

        if (tid < 64) {
            const float xi = z_s[jj]      + zi;
            const float xf = z_s[16 + jj] + zf;
            const float xg = z_s[32 + jj] + zg;
            const float xo = z_s[48 + jj] + zo;
            const float ig = fsigm(xi);
            const float fg = fsigm(xf);
            const float gg = ftanh(xg);
            const float og = fsigm(xo);
            c_reg = fg * c_reg + ig * gg;
            const float h = og * ftanh(c_reg);

            if (grp == 0)
                g_hs[(size_t)t * 512 + dir * H2D + (int)rank * 16 + jj] = h;

            if (s != TT - 1) {
                const int nb = b ^ 1;
#pragma unroll
                for (int u = 0; u < 4; u++)
                    st_async_f32(dst_h[nb][u], h, dst_m[nb][u]);
            }
        }
    }
}

// ---------------------------------------------------------------------------
// Kernel 3: logits = hs @ w_lin^T + b_lin.  One warp per timestep.
// ---------------------------------------------------------------------------
__global__ __launch_bounds__(256) void linear_kernel(
    const float* __restrict__ wlin, const float* __restrict__ blin)
{
    const int warp = threadIdx.x >> 5;
    const int lane = threadIdx.x & 31;
    const int t = blockIdx.x * 8 + warp;

    const float4* hrow = (const float4*)(g_hs + (size_t)t * 512);
    const float4* wrow = (const float4*)(wlin + (size_t)lane * 512);
    float acc = blin[lane];
#pragma unroll 8
    for (int m = 0; m < 128; m++) {
        const float4 h4 = hrow[m];
        const float4 w4 = wrow[m];
        acc += h4.x * w4.x + h4.y * w4.y + h4.z * w4.z + h4.w * w4.w;
    }
    g_logits[(size_t)t * LDIM + lane] = acc;
}

// ---------------------------------------------------------------------------
// Kernel 4: CRF negative log-likelihood. Single warp, E = exp(trans) matvec.
// ---------------------------------------------------------------------------
__global__ void crf_kernel(const float* __restrict__ trans,
                           const int* __restrict__ target,
                           float* __restrict__ out)
{
    __shared__ float tr_s[32 * 33];
    __shared__ float E_s[32 * 33];
    __shared__ float e_s[32];

    const int tid = threadIdx.x;   // blockDim = 32

    for (int i = tid; i < 1024; i += 32) {
        const int n = i >> 5, p = i & 31;
        const float v = trans[i];
        tr_s[n * 33 + p] = v;
        E_s[n * 33 + p]  = __expf(v);
    }
    __syncwarp();

    // ---- gold path score ----
    float gs = 0.f;
    for (int t = tid; t < TT; t += 32) {
        const int nxt  = target[t];
        const int prev = (t == 0) ? 0 : target[t - 1];
        gs += tr_s[nxt * 33 + prev] + g_logits[(size_t)t * LDIM + nxt];
    }
#pragma unroll
    for (int o = 16; o; o >>= 1) gs += __shfl_xor_sync(0xffffffffu, gs, o);
    gs += tr_s[31 * 33 + target[TT - 1]];

    // ---- forward algorithm ----
    const int n = tid;
    float a = tr_s[n * 33 + 0] + g_logits[n];
    const float* EP = &E_s[n * 33];

    for (int t = 1; t < TT; t++) {
        const float em = g_logits[(size_t)t * LDIM + n];
        const float M  = __shfl_sync(0xffffffffu, a, 1);
        e_s[n] = __expf(a - M);
        __syncwarp();
        float a0 = 0.f, a1 = 0.f, a2 = 0.f, a3 = 0.f;
#pragma unroll
        for (int p = 0; p < 32; p += 4) {
            a0 += e_s[p]     * EP[p];
            a1 += e_s[p + 1] * EP[p + 1];
            a2 += e_s[p + 2] * EP[p + 2];
            a3 += e_s[p + 3] * EP[p + 3];
        }
        const float ssum = (a0 + a1) + (a2 + a3);
        a = __logf(ssum) + M + em;
        __syncwarp();
    }

    const float v = a + tr_s[31 * 33 + n];
    float m = v;
#pragma unroll
    for (int o = 16; o; o >>= 1) m = fmaxf(m, __shfl_xor_sync(0xffffffffu, m, o));
    float ex = __expf(v - m);
#pragma unroll
    for (int o = 16; o; o >>= 1) ex += __shfl_xor_sync(0xffffffffu, ex, o);
    const float fwd = __logf(ex) + m;

    if (tid == 0) out[0] = fwd - gs;
}

// ---------------------------------------------------------------------------
// Launch
// ---------------------------------------------------------------------------
extern "C" void kernel_launch(void* const* d_in, const int* in_sizes, int n_in,
                              void* d_out, int out_size)
{
    const int*   ids    = (const int*)  d_in[0];
    const int*   target = (const int*)  d_in[2];
    const float* emb    = (const float*)d_in[3];
    const float* wihf   = (const float*)d_in[4];
    const float* whhf   = (const float*)d_in[5];
    const float* bf     = (const float*)d_in[6];
    const float* wihb   = (const float*)d_in[7];
    const float* whhb   = (const float*)d_in[8];
    const float* bb     = (const float*)d_in[9];
    const float* wlin   = (const float*)d_in[10];
    const float* blin   = (const float*)d_in[11];
    const float* trans  = (const float*)d_in[12];
    const float* h0     = (const float*)d_in[13];
    const float* c0     = (const float*)d_in[14];

    // 16-CTA clusters require the non-portable cluster size opt-in.
    cudaFuncSetAttribute(lstm_kernel, cudaFuncAttributeNonPortableClusterSizeAllowed, 1);

    dim3 g1(RTOT / 64, TT / 64);
    zin_kernel<<<g1, 256>>>(ids, emb, wihf, wihb, bf, bb);
    lstm_kernel<<<32, 256>>>(whhf, whhb, h0, c0);
    linear_kernel<<<TT / 8, 256>>>(wlin, blin);
    crf_kernel<<<1, 32>>>(trans, target, (float*)d_out);
}